// round 5
// baseline (speedup 1.0000x reference)
#include <cuda_runtime.h>
#include <cuda_bf16.h>
#include <cstdint>

#define N_NODES 50000
#define N_EDGES 400000
#define IN_C 32
#define OUT_C 32
#define EDGE_DIM 16
#define HIDDEN 128
#define BN_EPS 1e-5f

#define SCAN_BLOCKS ((N_NODES + 255) / 256)  // 196
#define BN_BLOCKS 232

// fused kernel geometry
#define BM 32                      // nodes per block
#define NB ((N_NODES + BM - 1) / BM)   // 1563
#define CAP 384                    // max staged edges per chunk
#define FUSED_SMEM 102400

// ---------------- static device scratch (no allocations allowed) ------------
__device__ float g_h[(size_t)N_NODES * OUT_C];
__device__ int   g_hist[N_NODES];
__device__ int   g_off[N_NODES + 1];
__device__ int   g_cursor[N_NODES];
__device__ int   g_perm[N_EDGES];
__device__ int   g_bsum[256];
__device__ int   g_boff[256];
__device__ double g_psum[BN_BLOCKS][OUT_C];
__device__ double g_psq[BN_BLOCKS][OUT_C];
__device__ float g_scale[OUT_C];
__device__ float g_shift[OUT_C];
__device__ int   g_is64;
// W2 pre-split into bf16 hi/lo planes, layout [kt][n][kpair] as packed u32
__device__ uint32_t g_w2h[128 * 512];
__device__ uint32_t g_w2l[128 * 512];

// ---------------- helpers ----------------------------------------------------
__device__ __forceinline__ void split_bf(float v, __nv_bfloat16& h,
                                         __nv_bfloat16& l) {
    h = __float2bfloat16_rn(v);
    l = __float2bfloat16_rn(v - __bfloat162float(h));
}

__device__ __forceinline__ uint32_t pack_bf(__nv_bfloat16 a, __nv_bfloat16 b) {
    __nv_bfloat162 p;
    p.x = a; p.y = b;
    return *reinterpret_cast<uint32_t*>(&p);
}

__device__ __forceinline__ uint32_t lds_u32(const __nv_bfloat16* p) {
    return *reinterpret_cast<const uint32_t*>(p);
}

__device__ __forceinline__ void mma16816(float c[4], uint32_t a0, uint32_t a1,
                                         uint32_t a2, uint32_t a3, uint32_t b0,
                                         uint32_t b1) {
    asm volatile(
        "mma.sync.aligned.m16n8k16.row.col.f32.bf16.bf16.f32 "
        "{%0,%1,%2,%3}, {%4,%5,%6,%7}, {%8,%9}, {%0,%1,%2,%3};"
        : "+f"(c[0]), "+f"(c[1]), "+f"(c[2]), "+f"(c[3])
        : "r"(a0), "r"(a1), "r"(a2), "r"(a3), "r"(b0), "r"(b1));
}

__device__ __forceinline__ int load_idx(const void* ei, int is64, long long elem) {
    int v = is64 ? (int)((const long long*)ei)[elem] : ((const int*)ei)[elem];
    return min(max(v, 0), N_NODES - 1);
}

// ---------------- W2 pre-split ----------------------------------------------
__global__ void k_w2prep(const float* __restrict__ w2) {
    int id = blockIdx.x * 256 + threadIdx.x;
    if (id < 128 * 512) {
        int kt = id >> 9, r = id & 511;
        int n = r >> 4, kp = r & 15;
        int k0 = kt * 32 + 2 * kp;
        float v0 = w2[(size_t)k0 * 32 + n];
        float v1 = w2[(size_t)(k0 + 1) * 32 + n];
        __nv_bfloat16 h0, l0, h1, l1;
        split_bf(v0, h0, l0);
        split_bf(v1, h1, l1);
        g_w2h[id] = pack_bf(h0, h1);
        g_w2l[id] = pack_bf(l0, l1);
    }
}

// ---------------- init + edge_index dtype detection --------------------------
__global__ void k_init(const void* ei) {
    if (blockIdx.x == 0 && threadIdx.x == 0) {
        const int* p = (const int*)ei;
        int is64 = 1;
        for (int i = 0; i < 512; i++)
            if (p[2 * i + 1] != 0) { is64 = 0; break; }
        g_is64 = is64;
    }
    for (int i = blockIdx.x * blockDim.x + threadIdx.x; i < N_NODES;
         i += gridDim.x * blockDim.x)
        g_hist[i] = 0;
}

// ---------------- histogram over dst ----------------------------------------
__global__ void k_hist(const void* __restrict__ ei) {
    int is64 = g_is64;
    for (int i = blockIdx.x * blockDim.x + threadIdx.x; i < N_EDGES;
         i += gridDim.x * blockDim.x) {
        int dst = load_idx(ei, is64, (long long)N_EDGES + i);
        atomicAdd(&g_hist[dst], 1);
    }
}

// ---------------- 3-kernel exclusive scan (256/block) -----------------------
__device__ __forceinline__ int block_excl_scan256(int v) {
    int tid = threadIdx.x;
    int lane = tid & 31, wid = tid >> 5;
    int incl = v;
#pragma unroll
    for (int o = 1; o < 32; o <<= 1) {
        int nv = __shfl_up_sync(0xffffffffu, incl, o);
        if (lane >= o) incl += nv;
    }
    __shared__ int ws[8];
    if (lane == 31) ws[wid] = incl;
    __syncthreads();
    if (wid == 0) {
        int wv = (lane < 8) ? ws[lane] : 0;
#pragma unroll
        for (int o = 1; o < 8; o <<= 1) {
            int nv = __shfl_up_sync(0xffffffffu, wv, o);
            if (lane >= o) wv += nv;
        }
        if (lane < 8) ws[lane] = wv;
    }
    __syncthreads();
    int base = (wid > 0) ? ws[wid - 1] : 0;
    return base + incl - v;
}

__global__ void k_scan_a() {
    int idx = blockIdx.x * 256 + threadIdx.x;
    int v = (idx < N_NODES) ? g_hist[idx] : 0;
    int ex = block_excl_scan256(v);
    if (threadIdx.x == 255) g_bsum[blockIdx.x] = ex + v;
}

__global__ void k_scan_b() {
    int tid = threadIdx.x;
    int v = (tid < SCAN_BLOCKS) ? g_bsum[tid] : 0;
    int ex = block_excl_scan256(v);
    if (tid < SCAN_BLOCKS) g_boff[tid] = ex;
    if (tid == 0) g_off[N_NODES] = N_EDGES;
}

__global__ void k_scan_c() {
    int idx = blockIdx.x * 256 + threadIdx.x;
    int v = (idx < N_NODES) ? g_hist[idx] : 0;
    int ex = block_excl_scan256(v) + g_boff[blockIdx.x];
    if (idx < N_NODES) {
        g_off[idx] = ex;
        g_cursor[idx] = ex;
    }
}

// ---------------- scatter edge ids grouped by dst ---------------------------
__global__ void k_scatter(const void* __restrict__ ei) {
    int is64 = g_is64;
    for (int i = blockIdx.x * blockDim.x + threadIdx.x; i < N_EDGES;
         i += gridDim.x * blockDim.x) {
        int dst = load_idx(ei, is64, (long long)N_EDGES + i);
        int pos = atomicAdd(&g_cursor[dst], 1);
        g_perm[pos] = i;
    }
}

// ---------------- fully fused: edge MLP + A-tile build + tensor-core GEMM ---
// block = 32 nodes, 256 threads. No g_A / g_H materialization.
__global__ void __launch_bounds__(256) k_fused(const float* __restrict__ x,
                                               const void* __restrict__ ei,
                                               const float* __restrict__ ea,
                                               const float* __restrict__ w1,
                                               const float* __restrict__ b1,
                                               const float* __restrict__ b2,
                                               const float* __restrict__ rw,
                                               const float* __restrict__ cb) {
    extern __shared__ __align__(16) unsigned char DYN[];
    float* s_xj  = (float*)DYN;                          // 49152 B
    float* s_ea  = (float*)(DYN + 49152);                // 24576 B
    float* s_w1t = (float*)(DYN + 73728);                // 8192 B  [kt][16]
    float* s_H   = (float*)(DYN + 81920);                // 1536 B
    __nv_bfloat16* s_Ah = (__nv_bfloat16*)(DYN + 83456); // 2560 B  [32][40]
    __nv_bfloat16* s_Al = (__nv_bfloat16*)(DYN + 86016); // 2560 B
    __nv_bfloat16* s_Wh = (__nv_bfloat16*)(DYN + 88576); // 5120 B  [2][32][40]
    __nv_bfloat16* s_Wl = (__nv_bfloat16*)(DYN + 93696); // 5120 B
    int* s_src = (int*)(DYN + 98816);                    // 1536 B
    int* s_e   = (int*)(DYN + 100352);                   // 1536 B
    int* s_nst = (int*)(DYN + 101888);                   // 144 B
    float* s_cb = (float*)(DYN + 102032);                // 128 B
    // epilogue aliases (inside s_xj region, used only after mainloop)
    float* C_s    = (float*)DYN;                         // 4096 B
    float* s_xsum = (float*)(DYN + 4096);                // 4096 B
    float* B2s    = (float*)(DYN + 8192);                // 4096 B
    float* RWs    = (float*)(DYN + 12288);               // 4096 B

    int tid = threadIdx.x, warp = tid >> 5, lane = tid & 31;
    int gi = lane >> 2, tq = lane & 3;
    int wm = warp & 1, wn = warp >> 1;
    int node = tid >> 3, ig = tid & 7;
    int rowbase = blockIdx.x * BM;
    int is64 = g_is64;

    // one-time staging: w1 transposed, node offsets
    for (int id = tid; id < HIDDEN * EDGE_DIM; id += 256)
        s_w1t[id] = w1[(id & 15) * HIDDEN + (id >> 4)];
    if (tid < 33) s_nst[tid] = g_off[min(rowbase + tid, N_NODES)];
    __syncthreads();

    int blockstart = s_nst[0], blockend = s_nst[32];

    float c[4] = {0.f, 0.f, 0.f, 0.f};
    float xs[4] = {0.f, 0.f, 0.f, 0.f};

    for (int estart = blockstart; estart < blockend; estart += CAP) {
        int cnt = min(blockend - estart, CAP);

        // ---- stage 1: edge ids + sources ----
        for (int j = tid; j < cnt; j += 256) {
            int e = g_perm[estart + j];
            s_e[j] = e;
            s_src[j] = load_idx(ei, is64, e);
        }
        __syncthreads();
        // ---- stage 2: gather x_j and ea ----
        for (int id = tid; id < cnt * 8; id += 256) {
            int j = id >> 3, q = id & 7;
            ((float4*)s_xj)[j * 8 + q] =
                ((const float4*)(x + (size_t)s_src[j] * IN_C))[q];
        }
        for (int id = tid; id < cnt * 4; id += 256) {
            int j = id >> 2, q = id & 3;
            ((float4*)s_ea)[j * 4 + q] =
                ((const float4*)(ea + (size_t)s_e[j] * EDGE_DIM))[q];
        }
        __syncthreads();

        // chunk-local edge range for this thread's node
        int ls = min(max(s_nst[node] - estart, 0), cnt);
        int le = min(max(s_nst[node + 1] - estart, 0), cnt);

        // xsum accumulation (kt-independent)
        for (int j = ls; j < le; j++) {
            xs[0] += s_xj[j * 32 + ig * 4 + 0];
            xs[1] += s_xj[j * 32 + ig * 4 + 1];
            xs[2] += s_xj[j * 32 + ig * 4 + 2];
            xs[3] += s_xj[j * 32 + ig * 4 + 3];
        }

        // ---- Wt prologue for kt = 0 (buffer 0) ----
        uint32_t wrh[2], wrl[2];
#pragma unroll
        for (int q = 0; q < 2; q++) {
            int id = tid + q * 256;
            wrh[q] = g_w2h[id];
            wrl[q] = g_w2l[id];
        }
#pragma unroll
        for (int q = 0; q < 2; q++) {
            int id = tid + q * 256;
            int n = id >> 4, kp = id & 15;
            ((uint32_t*)s_Wh)[n * 20 + kp] = wrh[q];
            ((uint32_t*)s_Wl)[n * 20 + kp] = wrl[q];
        }

        for (int kt = 0; kt < HIDDEN; kt++) {
            // prefetch next Wt tile (overlaps H phase)
            int ktn = (kt + 1 < HIDDEN) ? kt + 1 : kt;
#pragma unroll
            for (int q = 0; q < 2; q++) {
                int id = tid + q * 256;
                wrh[q] = g_w2h[ktn * 512 + id];
                wrl[q] = g_w2l[ktn * 512 + id];
            }

            // ---- phase A: H[e, kt] for chunk edges ----
            float4 wc0 = ((float4*)s_w1t)[kt * 4 + 0];
            float4 wc1 = ((float4*)s_w1t)[kt * 4 + 1];
            float4 wc2 = ((float4*)s_w1t)[kt * 4 + 2];
            float4 wc3 = ((float4*)s_w1t)[kt * 4 + 3];
            float b1v = __ldg(&b1[kt]);
            for (int j = tid; j < cnt; j += 256) {
                float4 e0 = ((float4*)s_ea)[j * 4 + 0];
                float4 e1 = ((float4*)s_ea)[j * 4 + 1];
                float4 e2 = ((float4*)s_ea)[j * 4 + 2];
                float4 e3 = ((float4*)s_ea)[j * 4 + 3];
                float he = b1v;
                he += e0.x * wc0.x + e0.y * wc0.y + e0.z * wc0.z + e0.w * wc0.w;
                he += e1.x * wc1.x + e1.y * wc1.y + e1.z * wc1.z + e1.w * wc1.w;
                he += e2.x * wc2.x + e2.y * wc2.y + e2.z * wc2.z + e2.w * wc2.w;
                he += e3.x * wc3.x + e3.y * wc3.y + e3.z * wc3.z + e3.w * wc3.w;
                s_H[j] = fmaxf(he, 0.f);
            }
            __syncthreads();

            // ---- phase B: A-tile build (fp32 -> bf16 hi/lo) + Wt STS ----
            float a0 = 0.f, a1 = 0.f, a2 = 0.f, a3 = 0.f;
            for (int j = ls; j < le; j++) {
                float he = s_H[j];
                float4 xv = ((float4*)s_xj)[j * 8 + ig];
                a0 += he * xv.x;
                a1 += he * xv.y;
                a2 += he * xv.z;
                a3 += he * xv.w;
            }
            {
                __nv_bfloat16 h0, l0, h1, l1, h2, l2, h3, l3;
                split_bf(a0, h0, l0); split_bf(a1, h1, l1);
                split_bf(a2, h2, l2); split_bf(a3, h3, l3);
                ((uint32_t*)s_Ah)[node * 20 + ig * 2] = pack_bf(h0, h1);
                ((uint32_t*)s_Ah)[node * 20 + ig * 2 + 1] = pack_bf(h2, h3);
                ((uint32_t*)s_Al)[node * 20 + ig * 2] = pack_bf(l0, l1);
                ((uint32_t*)s_Al)[node * 20 + ig * 2 + 1] = pack_bf(l2, l3);
            }
            {
                int nb = (kt + 1) & 1;
#pragma unroll
                for (int q = 0; q < 2; q++) {
                    int id = tid + q * 256;
                    int n = id >> 4, kp = id & 15;
                    ((uint32_t*)s_Wh)[nb * 640 + n * 20 + kp] = wrh[q];
                    ((uint32_t*)s_Wl)[nb * 640 + n * 20 + kp] = wrl[q];
                }
            }
            __syncthreads();

            // ---- phase C: MMA (3-pass hi/lo) ----
            {
                int cbuf = kt & 1;
                int arow = wm * 16 + gi;
#pragma unroll
                for (int kk = 0; kk < 32; kk += 16) {
                    const __nv_bfloat16* ah = &s_Ah[arow * 40 + kk + 2 * tq];
                    const __nv_bfloat16* al = &s_Al[arow * 40 + kk + 2 * tq];
                    uint32_t a0h = lds_u32(ah), a1h = lds_u32(ah + 8 * 40);
                    uint32_t a2h = lds_u32(ah + 8), a3h = lds_u32(ah + 8 * 40 + 8);
                    uint32_t a0l = lds_u32(al), a1l = lds_u32(al + 8 * 40);
                    uint32_t a2l = lds_u32(al + 8), a3l = lds_u32(al + 8 * 40 + 8);
                    const __nv_bfloat16* bh =
                        &s_Wh[cbuf * 1280 + (wn * 8 + gi) * 40 + kk + 2 * tq];
                    const __nv_bfloat16* bl =
                        &s_Wl[cbuf * 1280 + (wn * 8 + gi) * 40 + kk + 2 * tq];
                    uint32_t b0h = lds_u32(bh), b1h = lds_u32(bh + 8);
                    uint32_t b0l = lds_u32(bl), b1l = lds_u32(bl + 8);
                    mma16816(c, a0h, a1h, a2h, a3h, b0h, b1h);
                    mma16816(c, a0h, a1h, a2h, a3h, b0l, b1l);
                    mma16816(c, a0l, a1l, a2l, a3l, b0h, b1h);
                }
            }
            __syncthreads();
        }
    }

    // ---- epilogue: dump C + xsum, stage b2/rw, compute final h ----
    {
        int row = wm * 16 + gi;
        int col = wn * 8 + 2 * tq;
        C_s[row * 32 + col] = c[0];
        C_s[row * 32 + col + 1] = c[1];
        C_s[(row + 8) * 32 + col] = c[2];
        C_s[(row + 8) * 32 + col + 1] = c[3];
    }
    s_xsum[node * 32 + ig * 4 + 0] = xs[0];
    s_xsum[node * 32 + ig * 4 + 1] = xs[1];
    s_xsum[node * 32 + ig * 4 + 2] = xs[2];
    s_xsum[node * 32 + ig * 4 + 3] = xs[3];
    for (int id = tid; id < 1024; id += 256) {
        B2s[id] = b2[id];
        RWs[id] = rw[id];
    }
    if (tid < 32) s_cb[tid] = cb[tid];
    __syncthreads();

    int node_g = rowbase + node;
    if (node_g < N_NODES) {
        float cnt_f = (float)(s_nst[node + 1] - s_nst[node]);
        float inv = 1.f / fmaxf(cnt_f, 1.f);
        float xr[32];
        const float4* xp = (const float4*)(x + (size_t)node_g * IN_C);
#pragma unroll
        for (int q = 0; q < 8; q++) {
            float4 v = xp[q];
            xr[4 * q + 0] = v.x; xr[4 * q + 1] = v.y;
            xr[4 * q + 2] = v.z; xr[4 * q + 3] = v.w;
        }
#pragma unroll
        for (int q = 0; q < 4; q++) {
            int col = ig * 4 + q;
            float e0 = 0.f, r0 = 0.f;
#pragma unroll
            for (int i = 0; i < 32; i++) {
                e0 += s_xsum[node * 32 + i] * B2s[i * 32 + col];
                r0 += xr[i] * RWs[i * 32 + col];
            }
            g_h[(size_t)node_g * 32 + col] =
                (C_s[node * 32 + col] + e0) * inv + r0 + s_cb[col];
        }
    }
}

// ---------------- BatchNorm statistics (deterministic, no atomics) ----------
__global__ void k_bnstats() {
    int tid = threadIdx.x;  // 256
    int c = tid & 31, g = tid >> 5;
    double s = 0.0, s2 = 0.0;
    for (int row = blockIdx.x * 8 + g; row < N_NODES; row += gridDim.x * 8) {
        float v = g_h[(size_t)row * 32 + c];
        s += (double)v;
        s2 += (double)v * (double)v;
    }
    __shared__ double sh[256], sh2[256];
    sh[tid] = s; sh2[tid] = s2;
    __syncthreads();
    for (int off = 128; off >= 32; off >>= 1) {
        if (tid < off) { sh[tid] += sh[tid + off]; sh2[tid] += sh2[tid + off]; }
        __syncthreads();
    }
    if (tid < 32) {
        g_psum[blockIdx.x][tid] = sh[tid];
        g_psq[blockIdx.x][tid] = sh2[tid];
    }
}

__global__ void k_bnfin(const float* __restrict__ gamma,
                        const float* __restrict__ beta) {
    int c = threadIdx.x;
    if (c < OUT_C) {
        double s = 0.0, s2 = 0.0;
        for (int b = 0; b < BN_BLOCKS; b++) {
            s += g_psum[b][c];
            s2 += g_psq[b][c];
        }
        double mu = s / (double)N_NODES;
        double var = s2 / (double)N_NODES - mu * mu;
        float rstd = (float)rsqrt(var + (double)BN_EPS);
        float sc = rstd * gamma[c];
        g_scale[c] = sc;
        g_shift[c] = beta[c] - (float)mu * sc;
    }
}

// ---------------- output: x + relu(BN(h)) ------------------------------------
__global__ void k_out(const float* __restrict__ x, float* __restrict__ out) {
    int i = blockIdx.x * blockDim.x + threadIdx.x;
    const int total = N_NODES * OUT_C / 4;
    if (i < total) {
        float4 xv = ((const float4*)x)[i];
        float4 hv = ((const float4*)g_h)[i];
        int c = (i & 7) * 4;
        float4 o;
        o.x = xv.x + fmaxf(hv.x * g_scale[c + 0] + g_shift[c + 0], 0.f);
        o.y = xv.y + fmaxf(hv.y * g_scale[c + 1] + g_shift[c + 1], 0.f);
        o.z = xv.z + fmaxf(hv.z * g_scale[c + 2] + g_shift[c + 2], 0.f);
        o.w = xv.w + fmaxf(hv.w * g_scale[c + 3] + g_shift[c + 3], 0.f);
        ((float4*)out)[i] = o;
    }
}

// ---------------- launch -----------------------------------------------------
extern "C" void kernel_launch(void* const* d_in, const int* in_sizes, int n_in,
                              void* d_out, int out_size) {
    const float* x   = (const float*)d_in[0];
    const void*  ei  = d_in[1];               // int32 or int64, detected on device
    const float* ea  = (const float*)d_in[2];
    const float* w1  = (const float*)d_in[3];
    const float* b1  = (const float*)d_in[4];
    const float* w2  = (const float*)d_in[5];
    const float* b2  = (const float*)d_in[6];
    const float* rw  = (const float*)d_in[7];
    const float* cb  = (const float*)d_in[8];
    const float* gam = (const float*)d_in[9];
    const float* bet = (const float*)d_in[10];
    float* out = (float*)d_out;

    cudaFuncSetAttribute(k_fused, cudaFuncAttributeMaxDynamicSharedMemorySize,
                         FUSED_SMEM);

    k_w2prep<<<256, 256>>>(w2);
    k_init<<<196, 256>>>(ei);
    k_hist<<<512, 256>>>(ei);
    k_scan_a<<<SCAN_BLOCKS, 256>>>();
    k_scan_b<<<1, 256>>>();
    k_scan_c<<<SCAN_BLOCKS, 256>>>();
    k_scatter<<<512, 256>>>(ei);
    k_fused<<<NB, 256, FUSED_SMEM>>>(x, ei, ea, w1, b1, b2, rw, cb);
    k_bnstats<<<BN_BLOCKS, 256>>>();
    k_bnfin<<<1, 32>>>(gam, bet);
    k_out<<<(N_NODES * OUT_C / 4 + 255) / 256, 256>>>(x, out);
}

// round 6
// speedup vs baseline: 1.3722x; 1.3722x over previous
#include <cuda_runtime.h>
#include <cuda_bf16.h>
#include <cstdint>

#define N_NODES 50000
#define N_EDGES 400000
#define IN_C 32
#define OUT_C 32
#define EDGE_DIM 16
#define HIDDEN 128
#define BN_EPS 1e-5f

#define A_COLS (HIDDEN * IN_C)   // 4096
#define A_U32 (A_COLS / 2)       // 2048 packed u32 per node per plane
#define SCAN_BLOCKS ((N_NODES + 255) / 256)  // 196
#define BN_BLOCKS 232

// GEMM tiling
#define BM 128
#define BK 32
#define NKT (A_COLS / BK)  // 128
#define ASTR 40   // bf16 row stride in smem: conflict-free mma fragment LDS
#define WSTR 40

// abuild chunking
#define EDGE_CHUNK 256

// ---------------- static device scratch (no allocations allowed) ------------
__device__ uint32_t g_Ah[(size_t)N_NODES * A_U32];     // 410 MB (bf16 hi pairs)
__device__ uint32_t g_Al[(size_t)N_NODES * A_U32];     // 410 MB (bf16 lo pairs)
__device__ uint32_t g_w2h[128 * 512];                  // W2 hi plane [kt][n][kp]
__device__ uint32_t g_w2l[128 * 512];
__device__ float g_xsum[(size_t)N_NODES * IN_C];
__device__ float g_h[(size_t)N_NODES * OUT_C];
__device__ int   g_hist[N_NODES];
__device__ int   g_off[N_NODES + 1];
__device__ int   g_cursor[N_NODES];
__device__ int   g_perm[N_EDGES];
__device__ int   g_bsum[256];
__device__ int   g_boff[256];
__device__ double g_psum[BN_BLOCKS][OUT_C];
__device__ double g_psq[BN_BLOCKS][OUT_C];
__device__ float g_scale[OUT_C];
__device__ float g_shift[OUT_C];
__device__ int   g_is64;

// ---------------- helpers ----------------------------------------------------
__device__ __forceinline__ void split_bf(float v, __nv_bfloat16& h,
                                         __nv_bfloat16& l) {
    h = __float2bfloat16_rn(v);
    l = __float2bfloat16_rn(v - __bfloat162float(h));
}

__device__ __forceinline__ uint32_t pack_bf(__nv_bfloat16 a, __nv_bfloat16 b) {
    __nv_bfloat162 p;
    p.x = a; p.y = b;
    return *reinterpret_cast<uint32_t*>(&p);
}

__device__ __forceinline__ uint32_t lds_u32(const __nv_bfloat16* p) {
    return *reinterpret_cast<const uint32_t*>(p);
}

__device__ __forceinline__ void mma16816(float c[4], uint32_t a0, uint32_t a1,
                                         uint32_t a2, uint32_t a3, uint32_t b0,
                                         uint32_t b1) {
    asm volatile(
        "mma.sync.aligned.m16n8k16.row.col.f32.bf16.bf16.f32 "
        "{%0,%1,%2,%3}, {%4,%5,%6,%7}, {%8,%9}, {%0,%1,%2,%3};"
        : "+f"(c[0]), "+f"(c[1]), "+f"(c[2]), "+f"(c[3])
        : "r"(a0), "r"(a1), "r"(a2), "r"(a3), "r"(b0), "r"(b1));
}

__device__ __forceinline__ int load_idx(const void* ei, int is64, long long elem) {
    int v = is64 ? (int)((const long long*)ei)[elem] : ((const int*)ei)[elem];
    return min(max(v, 0), N_NODES - 1);
}

// ---------------- init: dtype detect + hist zero + W2 split -----------------
__global__ void k_init(const void* ei, const float* __restrict__ w2) {
    if (blockIdx.x == 0 && threadIdx.x == 0) {
        const int* p = (const int*)ei;
        int is64 = 1;
        for (int i = 0; i < 512; i++)
            if (p[2 * i + 1] != 0) { is64 = 0; break; }
        g_is64 = is64;
    }
    for (int i = blockIdx.x * blockDim.x + threadIdx.x; i < N_NODES;
         i += gridDim.x * blockDim.x)
        g_hist[i] = 0;
    // W2 pre-split: layout [kt][n][kpair] packed u32
    for (int id = blockIdx.x * blockDim.x + threadIdx.x; id < 128 * 512;
         id += gridDim.x * blockDim.x) {
        int kt = id >> 9, r = id & 511;
        int n = r >> 4, kp = r & 15;
        int k0 = kt * 32 + 2 * kp;
        float v0 = w2[(size_t)k0 * 32 + n];
        float v1 = w2[(size_t)(k0 + 1) * 32 + n];
        __nv_bfloat16 h0, l0, h1, l1;
        split_bf(v0, h0, l0);
        split_bf(v1, h1, l1);
        g_w2h[id] = pack_bf(h0, h1);
        g_w2l[id] = pack_bf(l0, l1);
    }
}

// ---------------- histogram over dst ----------------------------------------
__global__ void k_hist(const void* __restrict__ ei) {
    int is64 = g_is64;
    for (int i = blockIdx.x * blockDim.x + threadIdx.x; i < N_EDGES;
         i += gridDim.x * blockDim.x) {
        int dst = load_idx(ei, is64, (long long)N_EDGES + i);
        atomicAdd(&g_hist[dst], 1);
    }
}

// ---------------- 3-kernel exclusive scan (256/block) -----------------------
__device__ __forceinline__ int block_excl_scan256(int v) {
    int tid = threadIdx.x;
    int lane = tid & 31, wid = tid >> 5;
    int incl = v;
#pragma unroll
    for (int o = 1; o < 32; o <<= 1) {
        int nv = __shfl_up_sync(0xffffffffu, incl, o);
        if (lane >= o) incl += nv;
    }
    __shared__ int ws[8];
    if (lane == 31) ws[wid] = incl;
    __syncthreads();
    if (wid == 0) {
        int wv = (lane < 8) ? ws[lane] : 0;
#pragma unroll
        for (int o = 1; o < 8; o <<= 1) {
            int nv = __shfl_up_sync(0xffffffffu, wv, o);
            if (lane >= o) wv += nv;
        }
        if (lane < 8) ws[lane] = wv;
    }
    __syncthreads();
    int base = (wid > 0) ? ws[wid - 1] : 0;
    return base + incl - v;
}

__global__ void k_scan_a() {
    int idx = blockIdx.x * 256 + threadIdx.x;
    int v = (idx < N_NODES) ? g_hist[idx] : 0;
    int ex = block_excl_scan256(v);
    if (threadIdx.x == 255) g_bsum[blockIdx.x] = ex + v;
}

__global__ void k_scan_b() {
    int tid = threadIdx.x;
    int v = (tid < SCAN_BLOCKS) ? g_bsum[tid] : 0;
    int ex = block_excl_scan256(v);
    if (tid < SCAN_BLOCKS) g_boff[tid] = ex;
    if (tid == 0) g_off[N_NODES] = N_EDGES;
}

__global__ void k_scan_c() {
    int idx = blockIdx.x * 256 + threadIdx.x;
    int v = (idx < N_NODES) ? g_hist[idx] : 0;
    int ex = block_excl_scan256(v) + g_boff[blockIdx.x];
    if (idx < N_NODES) {
        g_off[idx] = ex;
        g_cursor[idx] = ex;
    }
}

// ---------------- scatter edge ids grouped by dst ---------------------------
__global__ void k_scatter(const void* __restrict__ ei) {
    int is64 = g_is64;
    for (int i = blockIdx.x * blockDim.x + threadIdx.x; i < N_EDGES;
         i += gridDim.x * blockDim.x) {
        int dst = load_idx(ei, is64, (long long)N_EDGES + i);
        int pos = atomicAdd(&g_cursor[dst], 1);
        g_perm[pos] = i;
    }
}

// ---------------- A build with fused edge MLP, bf16 hi/lo output ------------
// block = one node, 128 threads (h = tid).
__global__ void __launch_bounds__(128) k_abuild(const float* __restrict__ x,
                                                const void* __restrict__ ei,
                                                const float* __restrict__ ea,
                                                const float* __restrict__ w1,
                                                const float* __restrict__ b1) {
    int n = blockIdx.x;
    int tid = threadIdx.x;
    int is64 = g_is64;
    int start = g_off[n], end = g_off[n + 1];
    int d = end - start;

    float w1r[EDGE_DIM];
#pragma unroll
    for (int k = 0; k < EDGE_DIM; k++) w1r[k] = w1[k * HIDDEN + tid];
    float b1v = b1[tid];

    __shared__ int s_src[EDGE_CHUNK];
    __shared__ int s_e[EDGE_CHUNK];
    __shared__ float4 s_ea[EDGE_CHUNK][4];

    float acc[IN_C];
#pragma unroll
    for (int i = 0; i < IN_C; i++) acc[i] = 0.f;
    float xs = 0.f;

    for (int base = 0; base < d; base += EDGE_CHUNK) {
        int cnt = min(d - base, EDGE_CHUNK);
        __syncthreads();
        for (int j = tid; j < cnt; j += 128) {
            int e = g_perm[start + base + j];
            s_e[j] = e;
            s_src[j] = load_idx(ei, is64, e);
        }
        __syncthreads();
        for (int idx = tid; idx < cnt * 4; idx += 128) {
            int j = idx >> 2, q = idx & 3;
            s_ea[j][q] = ((const float4*)(ea + (size_t)s_e[j] * EDGE_DIM))[q];
        }
        __syncthreads();
        for (int j = 0; j < cnt; j++) {
            int src = s_src[j];
            const float4* xp = (const float4*)(x + (size_t)src * IN_C);
            float4 xv[8];
#pragma unroll
            for (int q = 0; q < 8; q++) xv[q] = xp[q];
            float xsv = (tid < IN_C) ? x[(size_t)src * IN_C + tid] : 0.f;

            float4 e0 = s_ea[j][0], e1 = s_ea[j][1], e2 = s_ea[j][2],
                   e3 = s_ea[j][3];
            float he = b1v;
            he += e0.x * w1r[0] + e0.y * w1r[1] + e0.z * w1r[2] + e0.w * w1r[3];
            he += e1.x * w1r[4] + e1.y * w1r[5] + e1.z * w1r[6] + e1.w * w1r[7];
            he += e2.x * w1r[8] + e2.y * w1r[9] + e2.z * w1r[10] + e2.w * w1r[11];
            he += e3.x * w1r[12] + e3.y * w1r[13] + e3.z * w1r[14] + e3.w * w1r[15];
            he = fmaxf(he, 0.f);

#pragma unroll
            for (int q = 0; q < 8; q++) {
                acc[4 * q + 0] += he * xv[q].x;
                acc[4 * q + 1] += he * xv[q].y;
                acc[4 * q + 2] += he * xv[q].z;
                acc[4 * q + 3] += he * xv[q].w;
            }
            xs += xsv;
        }
    }

    // split to bf16 hi/lo, pack, store 16 u32 per plane (4x uint4)
    uint32_t ph[16], pl[16];
#pragma unroll
    for (int m = 0; m < 16; m++) {
        __nv_bfloat16 h0, l0, h1, l1;
        split_bf(acc[2 * m], h0, l0);
        split_bf(acc[2 * m + 1], h1, l1);
        ph[m] = pack_bf(h0, h1);
        pl[m] = pack_bf(l0, l1);
    }
    uint4* aph = (uint4*)(g_Ah + (size_t)n * A_U32 + tid * 16);
    uint4* apl = (uint4*)(g_Al + (size_t)n * A_U32 + tid * 16);
#pragma unroll
    for (int q = 0; q < 4; q++) {
        aph[q] = make_uint4(ph[4 * q], ph[4 * q + 1], ph[4 * q + 2], ph[4 * q + 3]);
        apl[q] = make_uint4(pl[4 * q], pl[4 * q + 1], pl[4 * q + 2], pl[4 * q + 3]);
    }
    if (tid < IN_C) g_xsum[n * IN_C + tid] = xs;
}

// ---------------- main GEMM on tensor cores (pre-split bf16, 3 passes) ------
// Software-pipelined: LDG for kt+1 issued before MMAs of kt.
__global__ void __launch_bounds__(256) k_gemm(const float* __restrict__ x,
                                              const float* __restrict__ b2,
                                              const float* __restrict__ rw,
                                              const float* __restrict__ cb) {
    __shared__ __align__(16) unsigned char SMEM[25600];
    __nv_bfloat16* A_hi = (__nv_bfloat16*)SMEM;                    // 10240 B
    __nv_bfloat16* A_lo = (__nv_bfloat16*)(SMEM + 10240);          // 10240 B
    __nv_bfloat16* Wt_hi = (__nv_bfloat16*)(SMEM + 20480);         // 2560 B
    __nv_bfloat16* Wt_lo = (__nv_bfloat16*)(SMEM + 23040);         // 2560 B
    float* C_s = (float*)SMEM;  // 16 KB alias, used after the mainloop
    __shared__ float B2s[1024], RWs[1024], cbs[32];

    int tid = threadIdx.x;
    int warp = tid >> 5, lane = tid & 31;
    int gi = lane >> 2, tq = lane & 3;
    int rowbase = blockIdx.x * BM;

#pragma unroll
    for (int q = 0; q < 4; q++) {
        int id = tid + q * 256;
        B2s[id] = b2[id];
        RWs[id] = rw[id];
    }
    if (tid < 32) cbs[tid] = cb[tid];

    float c[4][4];
#pragma unroll
    for (int j = 0; j < 4; j++)
#pragma unroll
        for (int r = 0; r < 4; r++) c[j][r] = 0.f;

    int lrow = tid >> 1, half = tid & 1;
    bool rowok = (rowbase + lrow) < N_NODES;
    // per-row A source: 4 uint4 per kt (16 u32); this thread covers its half
    const uint4* ahsrc =
        (const uint4*)(g_Ah + (size_t)(rowbase + lrow) * A_U32) + half * 2;
    const uint4* alsrc =
        (const uint4*)(g_Al + (size_t)(rowbase + lrow) * A_U32) + half * 2;

    uint4 vah[2], val[2];
    uint32_t wrh[2], wrl[2];

    // ---- prologue: load + store kt = 0 ----
#pragma unroll
    for (int q = 0; q < 2; q++) {
        vah[q] = rowok ? ahsrc[q] : make_uint4(0, 0, 0, 0);
        val[q] = rowok ? alsrc[q] : make_uint4(0, 0, 0, 0);
    }
#pragma unroll
    for (int q = 0; q < 2; q++) {
        int id = tid + q * 256;
        wrh[q] = g_w2h[id];
        wrl[q] = g_w2l[id];
    }
    {
        uint4* dh = (uint4*)((uint32_t*)A_hi + lrow * 20 + half * 8);
        uint4* dl = (uint4*)((uint32_t*)A_lo + lrow * 20 + half * 8);
        dh[0] = vah[0]; dh[1] = vah[1];
        dl[0] = val[0]; dl[1] = val[1];
#pragma unroll
        for (int q = 0; q < 2; q++) {
            int id = tid + q * 256;
            int n = id >> 4, kp = id & 15;
            ((uint32_t*)Wt_hi)[n * 20 + kp] = wrh[q];
            ((uint32_t*)Wt_lo)[n * 20 + kp] = wrl[q];
        }
    }
    __syncthreads();

    for (int kt = 0; kt < NKT; kt++) {
        // ---- prefetch kt+1 into registers (overlaps the MMAs below) ----
        int ktn = (kt + 1 < NKT) ? kt + 1 : kt;
#pragma unroll
        for (int q = 0; q < 2; q++) {
            vah[q] = rowok ? ahsrc[ktn * 4 + q] : make_uint4(0, 0, 0, 0);
            val[q] = rowok ? alsrc[ktn * 4 + q] : make_uint4(0, 0, 0, 0);
        }
#pragma unroll
        for (int q = 0; q < 2; q++) {
            int id = tid + q * 256;
            wrh[q] = g_w2h[ktn * 512 + id];
            wrl[q] = g_w2l[ktn * 512 + id];
        }

        // ---- MMAs for kt from smem ----
        int rb = warp * 16;
#pragma unroll
        for (int kk = 0; kk < BK; kk += 16) {
            const __nv_bfloat16* ah = &A_hi[(rb + gi) * ASTR + kk + 2 * tq];
            const __nv_bfloat16* al = &A_lo[(rb + gi) * ASTR + kk + 2 * tq];
            uint32_t a0h = lds_u32(ah), a1h = lds_u32(ah + 8 * ASTR);
            uint32_t a2h = lds_u32(ah + 8), a3h = lds_u32(ah + 8 * ASTR + 8);
            uint32_t a0l = lds_u32(al), a1l = lds_u32(al + 8 * ASTR);
            uint32_t a2l = lds_u32(al + 8), a3l = lds_u32(al + 8 * ASTR + 8);
#pragma unroll
            for (int j = 0; j < 4; j++) {
                const __nv_bfloat16* bh = &Wt_hi[(j * 8 + gi) * WSTR + kk + 2 * tq];
                const __nv_bfloat16* bl = &Wt_lo[(j * 8 + gi) * WSTR + kk + 2 * tq];
                uint32_t b0h = lds_u32(bh), b1h = lds_u32(bh + 8);
                uint32_t b0l = lds_u32(bl), b1l = lds_u32(bl + 8);
                mma16816(c[j], a0h, a1h, a2h, a3h, b0h, b1h);
                mma16816(c[j], a0h, a1h, a2h, a3h, b0l, b1l);
                mma16816(c[j], a0l, a1l, a2l, a3l, b0h, b1h);
            }
        }
        __syncthreads();   // all reads of smem tiles done

        if (kt + 1 < NKT) {
            uint4* dh = (uint4*)((uint32_t*)A_hi + lrow * 20 + half * 8);
            uint4* dl = (uint4*)((uint32_t*)A_lo + lrow * 20 + half * 8);
            dh[0] = vah[0]; dh[1] = vah[1];
            dl[0] = val[0]; dl[1] = val[1];
#pragma unroll
            for (int q = 0; q < 2; q++) {
                int id = tid + q * 256;
                int n = id >> 4, kp = id & 15;
                ((uint32_t*)Wt_hi)[n * 20 + kp] = wrh[q];
                ((uint32_t*)Wt_lo)[n * 20 + kp] = wrl[q];
            }
        }
        __syncthreads();   // smem tiles (kt+1) visible
    }

    // ---- dump accumulators to shared (aliases A planes) ----
    {
        int rb = warp * 16;
#pragma unroll
        for (int j = 0; j < 4; j++) {
            int col = j * 8 + 2 * tq;
            C_s[(rb + gi) * 32 + col] = c[j][0];
            C_s[(rb + gi) * 32 + col + 1] = c[j][1];
            C_s[(rb + gi + 8) * 32 + col] = c[j][2];
            C_s[(rb + gi + 8) * 32 + col + 1] = c[j][3];
        }
    }
    __syncthreads();

    // ---- epilogue: mean, b2 term, root term, conv bias ----
    {
        int row = tid >> 1, ch = tid & 1;
        int mg = rowbase + row;
        if (mg < N_NODES) {
            float cnt = (float)(g_off[mg + 1] - g_off[mg]);
            float inv = 1.f / fmaxf(cnt, 1.f);
            const float4* xsp = (const float4*)(g_xsum + (size_t)mg * IN_C);
            const float4* xp = (const float4*)(x + (size_t)mg * IN_C);
            float eacc[16], racc[16];
#pragma unroll
            for (int cjj = 0; cjj < 16; cjj++) { eacc[cjj] = 0.f; racc[cjj] = 0.f; }
#pragma unroll
            for (int i4 = 0; i4 < 8; i4++) {
                float4 xsv = xsp[i4];
                float4 xvv = xp[i4];
                float sv[4] = {xsv.x, xsv.y, xsv.z, xsv.w};
                float vv[4] = {xvv.x, xvv.y, xvv.z, xvv.w};
#pragma unroll
                for (int ii = 0; ii < 4; ii++) {
                    int i = i4 * 4 + ii;
#pragma unroll
                    for (int cjj = 0; cjj < 16; cjj++) {
                        int col = ch * 16 + cjj;
                        eacc[cjj] += sv[ii] * B2s[i * 32 + col];
                        racc[cjj] += vv[ii] * RWs[i * 32 + col];
                    }
                }
            }
#pragma unroll
            for (int cjj = 0; cjj < 16; cjj++) {
                int col = ch * 16 + cjj;
                g_h[(size_t)mg * 32 + col] =
                    (C_s[row * 32 + col] + eacc[cjj]) * inv + racc[cjj] + cbs[col];
            }
        }
    }
}

// ---------------- BatchNorm statistics (deterministic, no atomics) ----------
__global__ void k_bnstats() {
    int tid = threadIdx.x;  // 256
    int c = tid & 31, g = tid >> 5;
    double s = 0.0, s2 = 0.0;
    for (int row = blockIdx.x * 8 + g; row < N_NODES; row += gridDim.x * 8) {
        float v = g_h[(size_t)row * 32 + c];
        s += (double)v;
        s2 += (double)v * (double)v;
    }
    __shared__ double sh[256], sh2[256];
    sh[tid] = s; sh2[tid] = s2;
    __syncthreads();
    for (int off = 128; off >= 32; off >>= 1) {
        if (tid < off) { sh[tid] += sh[tid + off]; sh2[tid] += sh2[tid + off]; }
        __syncthreads();
    }
    if (tid < 32) {
        g_psum[blockIdx.x][tid] = sh[tid];
        g_psq[blockIdx.x][tid] = sh2[tid];
    }
}

__global__ void k_bnfin(const float* __restrict__ gamma,
                        const float* __restrict__ beta) {
    int c = threadIdx.x;
    if (c < OUT_C) {
        double s = 0.0, s2 = 0.0;
        for (int b = 0; b < BN_BLOCKS; b++) {
            s += g_psum[b][c];
            s2 += g_psq[b][c];
        }
        double mu = s / (double)N_NODES;
        double var = s2 / (double)N_NODES - mu * mu;
        float rstd = (float)rsqrt(var + (double)BN_EPS);
        float sc = rstd * gamma[c];
        g_scale[c] = sc;
        g_shift[c] = beta[c] - (float)mu * sc;
    }
}

// ---------------- output: x + relu(BN(h)) ------------------------------------
__global__ void k_out(const float* __restrict__ x, float* __restrict__ out) {
    int i = blockIdx.x * blockDim.x + threadIdx.x;
    const int total = N_NODES * OUT_C / 4;
    if (i < total) {
        float4 xv = ((const float4*)x)[i];
        float4 hv = ((const float4*)g_h)[i];
        int c = (i & 7) * 4;
        float4 o;
        o.x = xv.x + fmaxf(hv.x * g_scale[c + 0] + g_shift[c + 0], 0.f);
        o.y = xv.y + fmaxf(hv.y * g_scale[c + 1] + g_shift[c + 1], 0.f);
        o.z = xv.z + fmaxf(hv.z * g_scale[c + 2] + g_shift[c + 2], 0.f);
        o.w = xv.w + fmaxf(hv.w * g_scale[c + 3] + g_shift[c + 3], 0.f);
        ((float4*)out)[i] = o;
    }
}

// ---------------- launch -----------------------------------------------------
extern "C" void kernel_launch(void* const* d_in, const int* in_sizes, int n_in,
                              void* d_out, int out_size) {
    const float* x   = (const float*)d_in[0];
    const void*  ei  = d_in[1];               // int32 or int64, detected on device
    const float* ea  = (const float*)d_in[2];
    const float* w1  = (const float*)d_in[3];
    const float* b1  = (const float*)d_in[4];
    const float* w2  = (const float*)d_in[5];
    const float* b2  = (const float*)d_in[6];
    const float* rw  = (const float*)d_in[7];
    const float* cb  = (const float*)d_in[8];
    const float* gam = (const float*)d_in[9];
    const float* bet = (const float*)d_in[10];
    float* out = (float*)d_out;

    k_init<<<256, 256>>>(ei, w2);
    k_hist<<<512, 256>>>(ei);
    k_scan_a<<<SCAN_BLOCKS, 256>>>();
    k_scan_b<<<1, 256>>>();
    k_scan_c<<<SCAN_BLOCKS, 256>>>();
    k_scatter<<<512, 256>>>(ei);
    k_abuild<<<N_NODES, 128>>>(x, ei, ea, w1, b1);
    k_gemm<<<(N_NODES + BM - 1) / BM, 256>>>(x, b2, rw, cb);
    k_bnstats<<<BN_BLOCKS, 256>>>();
    k_bnfin<<<1, 32>>>(gam, bet);
    k_out<<<(N_NODES * OUT_C / 4 + 255) / 256, 256>>>(x, out);
}

// round 7
// speedup vs baseline: 1.6612x; 1.2106x over previous
#include <cuda_runtime.h>
#include <cuda_bf16.h>
#include <cstdint>

#define N_NODES 50000
#define N_EDGES 400000
#define IN_C 32
#define OUT_C 32
#define EDGE_DIM 16
#define HIDDEN 128
#define BN_EPS 1e-5f

#define A_COLS (HIDDEN * IN_C)   // 4096
#define A_U32 (A_COLS / 2)       // 2048 packed u32 per node per plane
#define BN_BLOCKS 232

// GEMM tiling
#define BM 128
#define BK 32
#define NKT (A_COLS / BK)  // 128
#define ASTR 40
#define WSTR 40

// abuild chunking
#define ECHUNK 128

// ---------------- static device scratch (no allocations allowed) ------------
__device__ uint32_t g_Ah[(size_t)N_NODES * A_U32];     // 410 MB (bf16 hi pairs)
__device__ uint32_t g_Al[(size_t)N_NODES * A_U32];     // 410 MB (bf16 lo pairs)
__device__ uint32_t g_w2h[128 * 512];                  // W2 hi plane [kt][n][kp]
__device__ uint32_t g_w2l[128 * 512];
__device__ float g_xsum[(size_t)N_NODES * IN_C];
__device__ float g_h[(size_t)N_NODES * OUT_C];
__device__ int   g_hist[N_NODES];   // zero at module load; re-zeroed by k_scan
__device__ int   g_off[N_NODES + 1];
__device__ int   g_cursor[N_NODES];
__device__ int   g_perm[N_EDGES];
__device__ double g_psum[BN_BLOCKS][OUT_C];
__device__ double g_psq[BN_BLOCKS][OUT_C];
__device__ float g_scale[OUT_C];
__device__ float g_shift[OUT_C];

// ---------------- helpers ----------------------------------------------------
__device__ __forceinline__ void split_bf(float v, __nv_bfloat16& h,
                                         __nv_bfloat16& l) {
    h = __float2bfloat16_rn(v);
    l = __float2bfloat16_rn(v - __bfloat162float(h));
}

__device__ __forceinline__ uint32_t pack_bf(__nv_bfloat16 a, __nv_bfloat16 b) {
    __nv_bfloat162 p;
    p.x = a; p.y = b;
    return *reinterpret_cast<uint32_t*>(&p);
}

__device__ __forceinline__ uint32_t lds_u32(const __nv_bfloat16* p) {
    return *reinterpret_cast<const uint32_t*>(p);
}

__device__ __forceinline__ void mma16816(float c[4], uint32_t a0, uint32_t a1,
                                         uint32_t a2, uint32_t a3, uint32_t b0,
                                         uint32_t b1) {
    asm volatile(
        "mma.sync.aligned.m16n8k16.row.col.f32.bf16.bf16.f32 "
        "{%0,%1,%2,%3}, {%4,%5,%6,%7}, {%8,%9}, {%0,%1,%2,%3};"
        : "+f"(c[0]), "+f"(c[1]), "+f"(c[2]), "+f"(c[3])
        : "r"(a0), "r"(a1), "r"(a2), "r"(a3), "r"(b0), "r"(b1));
}

// packed f32x2 ops (sm_100+)
__device__ __forceinline__ unsigned long long pack2(float a, float b) {
    unsigned long long r;
    asm("mov.b64 %0, {%1, %2};" : "=l"(r) : "f"(a), "f"(b));
    return r;
}
__device__ __forceinline__ void unpack2(unsigned long long v, float& a, float& b) {
    asm("mov.b64 {%0, %1}, %2;" : "=f"(a), "=f"(b) : "l"(v));
}
__device__ __forceinline__ void fma2(unsigned long long& d, unsigned long long a,
                                     unsigned long long b) {
    asm("fma.rn.f32x2 %0, %1, %2, %0;" : "+l"(d) : "l"(a), "l"(b));
}
__device__ __forceinline__ unsigned long long mul2(unsigned long long a,
                                                   unsigned long long b) {
    unsigned long long r;
    asm("mul.rn.f32x2 %0, %1, %2;" : "=l"(r) : "l"(a), "l"(b));
    return r;
}

// self-detecting edge-index load (int32 vs int64 buffer layout)
__device__ __forceinline__ int detect64(const void* ei) {
    const int* p = (const int*)ei;
    return (p[1] == 0) & (p[3] == 0) & (p[5] == 0) & (p[7] == 0);
}
__device__ __forceinline__ int load_idx(const void* ei, int is64, long long elem) {
    int v = is64 ? (int)((const long long*)ei)[elem] : ((const int*)ei)[elem];
    return min(max(v, 0), N_NODES - 1);
}

// ---------------- launch 1: histogram over dst + W2 pre-split ----------------
__global__ void k_hist(const void* __restrict__ ei, const float* __restrict__ w2) {
    int is64 = detect64(ei);
    for (int i = blockIdx.x * blockDim.x + threadIdx.x; i < N_EDGES;
         i += gridDim.x * blockDim.x) {
        int dst = load_idx(ei, is64, (long long)N_EDGES + i);
        atomicAdd(&g_hist[dst], 1);
    }
    // W2 pre-split: layout [kt][n][kpair] packed u32
    for (int id = blockIdx.x * blockDim.x + threadIdx.x; id < 128 * 512;
         id += gridDim.x * blockDim.x) {
        int kt = id >> 9, r = id & 511;
        int n = r >> 4, kp = r & 15;
        int k0 = kt * 32 + 2 * kp;
        float v0 = w2[(size_t)k0 * 32 + n];
        float v1 = w2[(size_t)(k0 + 1) * 32 + n];
        __nv_bfloat16 h0, l0, h1, l1;
        split_bf(v0, h0, l0);
        split_bf(v1, h1, l1);
        g_w2h[id] = pack_bf(h0, h1);
        g_w2l[id] = pack_bf(l0, l1);
    }
}

// ---------------- launch 2: single-block scan (also re-zeros g_hist) --------
__device__ __forceinline__ int block_excl_scan1024(int v, int* ws) {
    int tid = threadIdx.x;
    int lane = tid & 31, wid = tid >> 5;
    int incl = v;
#pragma unroll
    for (int o = 1; o < 32; o <<= 1) {
        int nv = __shfl_up_sync(0xffffffffu, incl, o);
        if (lane >= o) incl += nv;
    }
    if (lane == 31) ws[wid] = incl;
    __syncthreads();
    if (wid == 0) {
        int wv = ws[lane];
#pragma unroll
        for (int o = 1; o < 32; o <<= 1) {
            int nv = __shfl_up_sync(0xffffffffu, wv, o);
            if (lane >= o) wv += nv;
        }
        ws[lane] = wv;
    }
    __syncthreads();
    int base = (wid > 0) ? ws[wid - 1] : 0;
    return base + incl - v;
}

__global__ void __launch_bounds__(1024) k_scan() {
    __shared__ int ws[32];
    __shared__ int s_carry;
    int tid = threadIdx.x;
    if (tid == 0) s_carry = 0;
    __syncthreads();
    for (int base = 0; base < N_NODES; base += 1024) {
        int idx = base + tid;
        int v = (idx < N_NODES) ? g_hist[idx] : 0;
        int ex = block_excl_scan1024(v, ws);
        int c = s_carry;
        if (idx < N_NODES) {
            g_off[idx] = c + ex;
            g_cursor[idx] = c + ex;
            g_hist[idx] = 0;   // ready for next graph replay
        }
        __syncthreads();
        if (tid == 1023) s_carry = c + ex + v;
        __syncthreads();
    }
    if (tid == 0) g_off[N_NODES] = N_EDGES;
}

// ---------------- launch 3: scatter edge ids grouped by dst -----------------
__global__ void k_scatter(const void* __restrict__ ei) {
    int is64 = detect64(ei);
    for (int i = blockIdx.x * blockDim.x + threadIdx.x; i < N_EDGES;
         i += gridDim.x * blockDim.x) {
        int dst = load_idx(ei, is64, (long long)N_EDGES + i);
        int pos = atomicAdd(&g_cursor[dst], 1);
        g_perm[pos] = i;
    }
}

// ---------------- launch 4 (PROFILED): A build, fused MLP, f32x2 ------------
// block = one node, 128 threads (h = tid). All per-edge data staged in smem;
// inner loop is pure broadcast-LDS + dual-lane FFMA2.
__global__ void __launch_bounds__(128) k_abuild(const float* __restrict__ x,
                                                const void* __restrict__ ei,
                                                const float* __restrict__ ea,
                                                const float* __restrict__ w1,
                                                const float* __restrict__ b1) {
    int n = blockIdx.x;
    int tid = threadIdx.x;
    int is64 = detect64(ei);
    int start = g_off[n], end = g_off[n + 1];
    int d = end - start;

    // packed w1 pairs: w1r2[k] = (w1[2k][tid], w1[2k+1][tid])
    unsigned long long w1r2[8];
#pragma unroll
    for (int k = 0; k < 8; k++)
        w1r2[k] = pack2(w1[(2 * k) * HIDDEN + tid], w1[(2 * k + 1) * HIDDEN + tid]);
    float b1v = b1[tid];

    __shared__ int s_src[ECHUNK];
    __shared__ int s_e[ECHUNK];
    __shared__ __align__(16) float4 s_ea[ECHUNK][4];   // 8 KB
    __shared__ __align__(16) float4 s_xj[ECHUNK][8];   // 16 KB

    unsigned long long acc2[16];
#pragma unroll
    for (int m = 0; m < 16; m++) acc2[m] = 0ull;
    float xs = 0.f;

    for (int base = 0; base < d; base += ECHUNK) {
        int cnt = min(d - base, ECHUNK);
        __syncthreads();
        for (int j = tid; j < cnt; j += 128) {
            int e = g_perm[start + base + j];
            s_e[j] = e;
            s_src[j] = load_idx(ei, is64, e);
        }
        __syncthreads();
        for (int idx = tid; idx < cnt * 4; idx += 128) {
            int j = idx >> 2, q = idx & 3;
            s_ea[j][q] = ((const float4*)(ea + (size_t)s_e[j] * EDGE_DIM))[q];
        }
        for (int idx = tid; idx < cnt * 8; idx += 128) {
            int j = idx >> 3, q = idx & 7;
            s_xj[j][q] = ((const float4*)(x + (size_t)s_src[j] * IN_C))[q];
        }
        __syncthreads();

        for (int j = 0; j < cnt; j++) {
            const unsigned long long* eap =
                (const unsigned long long*)&s_ea[j][0];   // 8 ull (broadcast LDS)
            unsigned long long h2 = mul2(eap[0], w1r2[0]);
#pragma unroll
            for (int k = 1; k < 8; k++) fma2(h2, eap[k], w1r2[k]);
            float hlo, hhi;
            unpack2(h2, hlo, hhi);
            float he = fmaxf(hlo + hhi + b1v, 0.f);
            unsigned long long he2 = pack2(he, he);

            const unsigned long long* xp2 =
                (const unsigned long long*)&s_xj[j][0];   // 16 ull (broadcast LDS)
#pragma unroll
            for (int m = 0; m < 16; m++) fma2(acc2[m], he2, xp2[m]);

            if (tid < IN_C) xs += ((const float*)s_xj)[j * 32 + tid];
        }
    }

    // unpack, split to bf16 hi/lo, pack, store 16 u32 per plane
    uint32_t ph[16], pl[16];
#pragma unroll
    for (int m = 0; m < 16; m++) {
        float a0, a1;
        unpack2(acc2[m], a0, a1);
        __nv_bfloat16 h0, l0, h1, l1;
        split_bf(a0, h0, l0);
        split_bf(a1, h1, l1);
        ph[m] = pack_bf(h0, h1);
        pl[m] = pack_bf(l0, l1);
    }
    uint4* aph = (uint4*)(g_Ah + (size_t)n * A_U32 + tid * 16);
    uint4* apl = (uint4*)(g_Al + (size_t)n * A_U32 + tid * 16);
#pragma unroll
    for (int q = 0; q < 4; q++) {
        aph[q] = make_uint4(ph[4 * q], ph[4 * q + 1], ph[4 * q + 2], ph[4 * q + 3]);
        apl[q] = make_uint4(pl[4 * q], pl[4 * q + 1], pl[4 * q + 2], pl[4 * q + 3]);
    }
    if (tid < IN_C) g_xsum[n * IN_C + tid] = xs;
}

// ---------------- launch 5: main GEMM on tensor cores (unchanged R6) --------
__global__ void __launch_bounds__(256) k_gemm(const float* __restrict__ x,
                                              const float* __restrict__ b2,
                                              const float* __restrict__ rw,
                                              const float* __restrict__ cb) {
    __shared__ __align__(16) unsigned char SMEM[25600];
    __nv_bfloat16* A_hi = (__nv_bfloat16*)SMEM;
    __nv_bfloat16* A_lo = (__nv_bfloat16*)(SMEM + 10240);
    __nv_bfloat16* Wt_hi = (__nv_bfloat16*)(SMEM + 20480);
    __nv_bfloat16* Wt_lo = (__nv_bfloat16*)(SMEM + 23040);
    float* C_s = (float*)SMEM;
    __shared__ float B2s[1024], RWs[1024], cbs[32];

    int tid = threadIdx.x;
    int warp = tid >> 5, lane = tid & 31;
    int gi = lane >> 2, tq = lane & 3;
    int rowbase = blockIdx.x * BM;

#pragma unroll
    for (int q = 0; q < 4; q++) {
        int id = tid + q * 256;
        B2s[id] = b2[id];
        RWs[id] = rw[id];
    }
    if (tid < 32) cbs[tid] = cb[tid];

    float c[4][4];
#pragma unroll
    for (int j = 0; j < 4; j++)
#pragma unroll
        for (int r = 0; r < 4; r++) c[j][r] = 0.f;

    int lrow = tid >> 1, half = tid & 1;
    bool rowok = (rowbase + lrow) < N_NODES;
    const uint4* ahsrc =
        (const uint4*)(g_Ah + (size_t)(rowbase + lrow) * A_U32) + half * 2;
    const uint4* alsrc =
        (const uint4*)(g_Al + (size_t)(rowbase + lrow) * A_U32) + half * 2;

    uint4 vah[2], val[2];
    uint32_t wrh[2], wrl[2];

#pragma unroll
    for (int q = 0; q < 2; q++) {
        vah[q] = rowok ? ahsrc[q] : make_uint4(0, 0, 0, 0);
        val[q] = rowok ? alsrc[q] : make_uint4(0, 0, 0, 0);
    }
#pragma unroll
    for (int q = 0; q < 2; q++) {
        int id = tid + q * 256;
        wrh[q] = g_w2h[id];
        wrl[q] = g_w2l[id];
    }
    {
        uint4* dh = (uint4*)((uint32_t*)A_hi + lrow * 20 + half * 8);
        uint4* dl = (uint4*)((uint32_t*)A_lo + lrow * 20 + half * 8);
        dh[0] = vah[0]; dh[1] = vah[1];
        dl[0] = val[0]; dl[1] = val[1];
#pragma unroll
        for (int q = 0; q < 2; q++) {
            int id = tid + q * 256;
            int n = id >> 4, kp = id & 15;
            ((uint32_t*)Wt_hi)[n * 20 + kp] = wrh[q];
            ((uint32_t*)Wt_lo)[n * 20 + kp] = wrl[q];
        }
    }
    __syncthreads();

    for (int kt = 0; kt < NKT; kt++) {
        int ktn = (kt + 1 < NKT) ? kt + 1 : kt;
#pragma unroll
        for (int q = 0; q < 2; q++) {
            vah[q] = rowok ? ahsrc[ktn * 4 + q] : make_uint4(0, 0, 0, 0);
            val[q] = rowok ? alsrc[ktn * 4 + q] : make_uint4(0, 0, 0, 0);
        }
#pragma unroll
        for (int q = 0; q < 2; q++) {
            int id = tid + q * 256;
            wrh[q] = g_w2h[ktn * 512 + id];
            wrl[q] = g_w2l[ktn * 512 + id];
        }

        int rb = warp * 16;
#pragma unroll
        for (int kk = 0; kk < BK; kk += 16) {
            const __nv_bfloat16* ah = &A_hi[(rb + gi) * ASTR + kk + 2 * tq];
            const __nv_bfloat16* al = &A_lo[(rb + gi) * ASTR + kk + 2 * tq];
            uint32_t a0h = lds_u32(ah), a1h = lds_u32(ah + 8 * ASTR);
            uint32_t a2h = lds_u32(ah + 8), a3h = lds_u32(ah + 8 * ASTR + 8);
            uint32_t a0l = lds_u32(al), a1l = lds_u32(al + 8 * ASTR);
            uint32_t a2l = lds_u32(al + 8), a3l = lds_u32(al + 8 * ASTR + 8);
#pragma unroll
            for (int j = 0; j < 4; j++) {
                const __nv_bfloat16* bh = &Wt_hi[(j * 8 + gi) * WSTR + kk + 2 * tq];
                const __nv_bfloat16* bl = &Wt_lo[(j * 8 + gi) * WSTR + kk + 2 * tq];
                uint32_t b0h = lds_u32(bh), b1h = lds_u32(bh + 8);
                uint32_t b0l = lds_u32(bl), b1l = lds_u32(bl + 8);
                mma16816(c[j], a0h, a1h, a2h, a3h, b0h, b1h);
                mma16816(c[j], a0h, a1h, a2h, a3h, b0l, b1l);
                mma16816(c[j], a0l, a1l, a2l, a3l, b0h, b1h);
            }
        }
        __syncthreads();

        if (kt + 1 < NKT) {
            uint4* dh = (uint4*)((uint32_t*)A_hi + lrow * 20 + half * 8);
            uint4* dl = (uint4*)((uint32_t*)A_lo + lrow * 20 + half * 8);
            dh[0] = vah[0]; dh[1] = vah[1];
            dl[0] = val[0]; dl[1] = val[1];
#pragma unroll
            for (int q = 0; q < 2; q++) {
                int id = tid + q * 256;
                int n = id >> 4, kp = id & 15;
                ((uint32_t*)Wt_hi)[n * 20 + kp] = wrh[q];
                ((uint32_t*)Wt_lo)[n * 20 + kp] = wrl[q];
            }
        }
        __syncthreads();
    }

    {
        int rb = warp * 16;
#pragma unroll
        for (int j = 0; j < 4; j++) {
            int col = j * 8 + 2 * tq;
            C_s[(rb + gi) * 32 + col] = c[j][0];
            C_s[(rb + gi) * 32 + col + 1] = c[j][1];
            C_s[(rb + gi + 8) * 32 + col] = c[j][2];
            C_s[(rb + gi + 8) * 32 + col + 1] = c[j][3];
        }
    }
    __syncthreads();

    {
        int row = tid >> 1, ch = tid & 1;
        int mg = rowbase + row;
        if (mg < N_NODES) {
            float cnt = (float)(g_off[mg + 1] - g_off[mg]);
            float inv = 1.f / fmaxf(cnt, 1.f);
            const float4* xsp = (const float4*)(g_xsum + (size_t)mg * IN_C);
            const float4* xp = (const float4*)(x + (size_t)mg * IN_C);
            float eacc[16], racc[16];
#pragma unroll
            for (int cjj = 0; cjj < 16; cjj++) { eacc[cjj] = 0.f; racc[cjj] = 0.f; }
#pragma unroll
            for (int i4 = 0; i4 < 8; i4++) {
                float4 xsv = xsp[i4];
                float4 xvv = xp[i4];
                float sv[4] = {xsv.x, xsv.y, xsv.z, xsv.w};
                float vv[4] = {xvv.x, xvv.y, xvv.z, xvv.w};
#pragma unroll
                for (int ii = 0; ii < 4; ii++) {
                    int i = i4 * 4 + ii;
#pragma unroll
                    for (int cjj = 0; cjj < 16; cjj++) {
                        int col = ch * 16 + cjj;
                        eacc[cjj] += sv[ii] * B2s[i * 32 + col];
                        racc[cjj] += vv[ii] * RWs[i * 32 + col];
                    }
                }
            }
#pragma unroll
            for (int cjj = 0; cjj < 16; cjj++) {
                int col = ch * 16 + cjj;
                g_h[(size_t)mg * 32 + col] =
                    (C_s[row * 32 + col] + eacc[cjj]) * inv + racc[cjj] + cbs[col];
            }
        }
    }
}

// ---------------- BatchNorm statistics (deterministic, no atomics) ----------
__global__ void k_bnstats() {
    int tid = threadIdx.x;  // 256
    int c = tid & 31, g = tid >> 5;
    double s = 0.0, s2 = 0.0;
    for (int row = blockIdx.x * 8 + g; row < N_NODES; row += gridDim.x * 8) {
        float v = g_h[(size_t)row * 32 + c];
        s += (double)v;
        s2 += (double)v * (double)v;
    }
    __shared__ double sh[256], sh2[256];
    sh[tid] = s; sh2[tid] = s2;
    __syncthreads();
    for (int off = 128; off >= 32; off >>= 1) {
        if (tid < off) { sh[tid] += sh[tid + off]; sh2[tid] += sh2[tid + off]; }
        __syncthreads();
    }
    if (tid < 32) {
        g_psum[blockIdx.x][tid] = sh[tid];
        g_psq[blockIdx.x][tid] = sh2[tid];
    }
}

__global__ void k_bnfin(const float* __restrict__ gamma,
                        const float* __restrict__ beta) {
    int c = threadIdx.x;
    if (c < OUT_C) {
        double s = 0.0, s2 = 0.0;
        for (int b = 0; b < BN_BLOCKS; b++) {
            s += g_psum[b][c];
            s2 += g_psq[b][c];
        }
        double mu = s / (double)N_NODES;
        double var = s2 / (double)N_NODES - mu * mu;
        float rstd = (float)rsqrt(var + (double)BN_EPS);
        float sc = rstd * gamma[c];
        g_scale[c] = sc;
        g_shift[c] = beta[c] - (float)mu * sc;
    }
}

// ---------------- output: x + relu(BN(h)) ------------------------------------
__global__ void k_out(const float* __restrict__ x, float* __restrict__ out) {
    int i = blockIdx.x * blockDim.x + threadIdx.x;
    const int total = N_NODES * OUT_C / 4;
    if (i < total) {
        float4 xv = ((const float4*)x)[i];
        float4 hv = ((const float4*)g_h)[i];
        int c = (i & 7) * 4;
        float4 o;
        o.x = xv.x + fmaxf(hv.x * g_scale[c + 0] + g_shift[c + 0], 0.f);
        o.y = xv.y + fmaxf(hv.y * g_scale[c + 1] + g_shift[c + 1], 0.f);
        o.z = xv.z + fmaxf(hv.z * g_scale[c + 2] + g_shift[c + 2], 0.f);
        o.w = xv.w + fmaxf(hv.w * g_scale[c + 3] + g_shift[c + 3], 0.f);
        ((float4*)out)[i] = o;
    }
}

// ---------------- launch -----------------------------------------------------
extern "C" void kernel_launch(void* const* d_in, const int* in_sizes, int n_in,
                              void* d_out, int out_size) {
    const float* x   = (const float*)d_in[0];
    const void*  ei  = d_in[1];               // int32 or int64, self-detected
    const float* ea  = (const float*)d_in[2];
    const float* w1  = (const float*)d_in[3];
    const float* b1  = (const float*)d_in[4];
    const float* w2  = (const float*)d_in[5];
    const float* b2  = (const float*)d_in[6];
    const float* rw  = (const float*)d_in[7];
    const float* cb  = (const float*)d_in[8];
    const float* gam = (const float*)d_in[9];
    const float* bet = (const float*)d_in[10];
    float* out = (float*)d_out;

    k_hist<<<512, 256>>>(ei, w2);             // launch 1
    k_scan<<<1, 1024>>>();                    // launch 2
    k_scatter<<<512, 256>>>(ei);              // launch 3
    k_abuild<<<N_NODES, 128>>>(x, ei, ea, w1, b1);  // launch 4 (profiled)
    k_gemm<<<(N_NODES + BM - 1) / BM, 256>>>(x, b2, rw, cb);
    k_bnstats<<<BN_BLOCKS, 256>>>();
    k_bnfin<<<1, 32>>>(gam, bet);
    k_out<<<(N_NODES * OUT_C / 4 + 255) / 256, 256>>>(x, out);
}